// round 4
// baseline (speedup 1.0000x reference)
#include <cuda_runtime.h>
#include <cstddef>

// Fixed problem shape: K=64, N=1048576, NS=1024, B=1024
constexpr int   Kdim   = 64;
constexpr long  Nn     = 1048576;
constexpr int   NSs    = 1024;
constexpr int   Bseq   = 1024;
constexpr int   TBLK   = 16;          // staging block (time steps)
constexpr int   STRIDE = 20;          // staged row stride in floats (16B aligned)
constexpr int   NBLK   = NSs / TBLK;  // 64
constexpr float L2E    = 1.4426950408889634f;
constexpr float LN2    = 0.6931471805599453f;

__device__ unsigned gT2[Kdim * 32];   // gT2[k*32+j] = bf16x2(Tp[2j][k], Tp[2j+1][k])
__device__ float    gLpi2[Kdim];      // log_softmax(pi) * log2(e)
__device__ float    gPart[Bseq];

// ---------------------------------------------------------------------------
// helpers
// ---------------------------------------------------------------------------
__device__ __forceinline__ float ex2f(float x) {
    float r; asm("ex2.approx.ftz.f32 %0, %1;" : "=f"(r) : "f"(x)); return r;
}
__device__ __forceinline__ float lg2f(float x) {
    float r; asm("lg2.approx.ftz.f32 %0, %1;" : "=f"(r) : "f"(x)); return r;
}
__device__ __forceinline__ float warp_sum(float v) {
#pragma unroll
    for (int o = 16; o > 0; o >>= 1) v += __shfl_xor_sync(0xffffffffu, v, o);
    return v;
}
__device__ __forceinline__ void hfma2(unsigned& acc, unsigned a, unsigned b) {
    asm("fma.rn.bf16x2 %0, %1, %2, %0;" : "+r"(acc) : "r"(a), "r"(b));
}
__device__ __forceinline__ float blo(unsigned u) { return __uint_as_float(u << 16); }
__device__ __forceinline__ float bhi(unsigned u) { return __uint_as_float(u & 0xffff0000u); }
__device__ __forceinline__ unsigned pack_bf16x2(float lo, float hi) {
    unsigned r; asm("cvt.rn.bf16x2.f32 %0, %1, %2;" : "=r"(r) : "f"(hi), "f"(lo)); return r;
}
__device__ __forceinline__ void cpasync16(void* dst, const void* src) {
    unsigned d = (unsigned)__cvta_generic_to_shared(dst);
    asm volatile("cp.async.ca.shared.global [%0], [%1], 16;" :: "r"(d), "l"(src));
}
template <int N> __device__ __forceinline__ void wait_group() {
    asm volatile("cp.async.wait_group %0;" :: "n"(N));
}
__device__ __forceinline__ void commit_group() {
    asm volatile("cp.async.commit_group;");
}

// stage one 16-step emission block (64 rows x 16 floats) for one sequence
__device__ __forceinline__ void stage(float* sbuf, const float* gbase, int l) {
#pragma unroll
    for (int i = 0; i < 8; i++) {
        int idx = (i << 5) + l;          // 0..255
        int row = idx >> 2;              // 0..63
        int c4  = (idx & 3) << 2;        // 0,4,8,12
        cpasync16(sbuf + row * STRIDE + c4, gbase + (size_t)row * Nn + c4);
    }
}

// ---------------------------------------------------------------------------
// prep (single CTA): Tp = softmax(T, rows) -> bf16x2 pack; gLpi2
// ---------------------------------------------------------------------------
__global__ void prep_kernel(const float* __restrict__ pi, const float* __restrict__ T) {
    __shared__ float sTp[Kdim * Kdim];
    int tid = threadIdx.x, w = tid >> 5, l = tid & 31;
#pragma unroll
    for (int r = w; r < Kdim; r += 32) {
        float a = T[r * Kdim + l], c = T[r * Kdim + l + 32];
        float m = fmaxf(a, c);
#pragma unroll
        for (int o = 16; o > 0; o >>= 1) m = fmaxf(m, __shfl_xor_sync(0xffffffffu, m, o));
        float ea = expf(a - m), ec = expf(c - m);
        float s = warp_sum(ea + ec);
        float inv = 1.0f / s;
        sTp[r * Kdim + l]      = ea * inv;
        sTp[r * Kdim + l + 32] = ec * inv;
    }
    __syncthreads();
    for (int idx = tid; idx < Kdim * 32; idx += 1024) {
        int k = idx >> 5, j = idx & 31;
        gT2[idx] = pack_bf16x2(sTp[(2 * j) * Kdim + k], sTp[(2 * j + 1) * Kdim + k]);
    }
    if (w == 0) {
        float pa = pi[l], pb = pi[l + 32];
        float m2 = fmaxf(pa, pb);
#pragma unroll
        for (int o = 16; o > 0; o >>= 1) m2 = fmaxf(m2, __shfl_xor_sync(0xffffffffu, m2, o));
        float sp = warp_sum(expf(pa - m2) + expf(pb - m2));
        float ls = logf(sp);
        gLpi2[l]      = (pa - m2 - ls) * L2E;
        gLpi2[l + 32] = (pb - m2 - ls) * L2E;
    }
}

// ---------------------------------------------------------------------------
// one forward step for TWO sequences (interleaved chains)
// lane l owns states (2l, 2l+1); q buffers: 32 bf16x2 words per seq
// ---------------------------------------------------------------------------
struct Q4 { float q0A, q0B, q1A, q1B; };

__device__ __forceinline__ void stepPair(
    const unsigned* qr0, unsigned* qw0,
    const unsigned* qr1, unsigned* qw1, int l,
    const unsigned* __restrict__ Ta, const unsigned* __restrict__ Tb,
    float e0A, float e0B, float e1A, float e1B,
    float gp0, float gp1, Q4& q)
{
    __syncwarp();
    const uint4* p0 = (const uint4*)qr0;
    const uint4* p1 = (const uint4*)qr1;
    unsigned A00 = 0, A01 = 0, B00 = 0, B01 = 0;
    unsigned A10 = 0, A11 = 0, B10 = 0, B11 = 0;
#pragma unroll
    for (int i = 0; i < 8; i++) {
        uint4 w0 = p0[i], w1 = p1[i];
        hfma2(A00, w0.x, Ta[4 * i + 0]); hfma2(B00, w0.x, Tb[4 * i + 0]);
        hfma2(A10, w1.x, Ta[4 * i + 0]); hfma2(B10, w1.x, Tb[4 * i + 0]);
        hfma2(A01, w0.y, Ta[4 * i + 1]); hfma2(B01, w0.y, Tb[4 * i + 1]);
        hfma2(A11, w1.y, Ta[4 * i + 1]); hfma2(B11, w1.y, Tb[4 * i + 1]);
        hfma2(A00, w0.z, Ta[4 * i + 2]); hfma2(B00, w0.z, Tb[4 * i + 2]);
        hfma2(A10, w1.z, Ta[4 * i + 2]); hfma2(B10, w1.z, Tb[4 * i + 2]);
        hfma2(A01, w0.w, Ta[4 * i + 3]); hfma2(B01, w0.w, Tb[4 * i + 3]);
        hfma2(A11, w1.w, Ta[4 * i + 3]); hfma2(B11, w1.w, Tb[4 * i + 3]);
    }
    // fp32 final combine (removes the full-magnitude bf16 rounding bias)
    float d0A = (blo(A00) + blo(A01)) + (bhi(A00) + bhi(A01));
    float d0B = (blo(B00) + blo(B01)) + (bhi(B00) + bhi(B01));
    float d1A = (blo(A10) + blo(A11)) + (bhi(A10) + bhi(A11));
    float d1B = (blo(B10) + blo(B11)) + (bhi(B10) + bhi(B11));
    q.q0A = ex2f(fmaf(e0A, L2E, gp0)) * d0A;
    q.q0B = ex2f(fmaf(e0B, L2E, gp0)) * d0B;
    q.q1A = ex2f(fmaf(e1A, L2E, gp1)) * d1A;
    q.q1B = ex2f(fmaf(e1B, L2E, gp1)) * d1B;
    qw0[l] = pack_bf16x2(q.q0A, q.q0B);
    qw1[l] = pack_bf16x2(q.q1A, q.q1B);
}

// 4 consecutive steps (t0 multiple of 4; first step reads buf1, writes buf0)
__device__ __forceinline__ void group4(
    const float* sb0, const float* sb1, int tt, int l,
    unsigned* q00, unsigned* q01, unsigned* q10, unsigned* q11,
    const unsigned* Ta, const unsigned* Tb,
    float gp0, float gp1, Q4& q)
{
    float4 eA0 = *(const float4*)(sb0 + (2 * l) * STRIDE + tt);
    float4 eB0 = *(const float4*)(sb0 + (2 * l + 1) * STRIDE + tt);
    float4 eA1 = *(const float4*)(sb1 + (2 * l) * STRIDE + tt);
    float4 eB1 = *(const float4*)(sb1 + (2 * l + 1) * STRIDE + tt);
    stepPair(q01, q00, q11, q10, l, Ta, Tb, eA0.x, eB0.x, eA1.x, eB1.x, gp0, gp1, q);
    stepPair(q00, q01, q10, q11, l, Ta, Tb, eA0.y, eB0.y, eA1.y, eB1.y, 0.f, 0.f, q);
    stepPair(q01, q00, q11, q10, l, Ta, Tb, eA0.z, eB0.z, eA1.z, eB1.z, 0.f, 0.f, q);
    stepPair(q00, q01, q10, q11, l, Ta, Tb, eA0.w, eB0.w, eA1.w, eB1.w, 0.f, 0.f, q);
}

// ---------------------------------------------------------------------------
// forward scan: one warp per CTA, TWO sequences per warp (512 CTAs)
// ---------------------------------------------------------------------------
__global__ void __launch_bounds__(32) fwd_kernel(const float* __restrict__ lp) {
    __shared__ float st[2][2][Kdim * STRIDE];          // [seq][buf]  20480 B
    __shared__ __align__(16) unsigned qsm[2][2][32];   // [seq][pingpong]
    const int l = threadIdx.x;
    const float* base0 = lp + (size_t)(2 * blockIdx.x) * NSs;
    const float* base1 = base0 + NSs;

    stage(st[0][0], base0, l);
    stage(st[1][0], base1, l);
    commit_group();
    stage(st[0][1], base0 + TBLK, l);
    stage(st[1][1], base1 + TBLK, l);
    commit_group();

    unsigned Ta[32], Tb[32];
#pragma unroll
    for (int j = 0; j < 32; j++) {
        Ta[j] = gT2[(2 * l) * 32 + j];
        Tb[j] = gT2[(2 * l + 1) * 32 + j];
    }
    const float lpiA = gLpi2[2 * l], lpiB = gLpi2[2 * l + 1];

    unsigned* q00 = qsm[0][0]; unsigned* q01 = qsm[0][1];
    unsigned* q10 = qsm[1][0]; unsigned* q11 = qsm[1][1];

    wait_group<1>();
    __syncwarp();

    Q4 q;
    float c0 = 0.f, c1 = 0.f, gp0 = 0.f, gp1 = 0.f;

    // ---- block 0 (group 0 special: t=0 init + steps 1..3) ----
    {
        const float* sb0 = st[0][0];
        const float* sb1 = st[1][0];
        float4 eA0 = *(const float4*)(sb0 + (2 * l) * STRIDE);
        float4 eB0 = *(const float4*)(sb0 + (2 * l + 1) * STRIDE);
        float4 eA1 = *(const float4*)(sb1 + (2 * l) * STRIDE);
        float4 eB1 = *(const float4*)(sb1 + (2 * l + 1) * STRIDE);
        q.q0A = ex2f(fmaf(eA0.x, L2E, lpiA));
        q.q0B = ex2f(fmaf(eB0.x, L2E, lpiB));
        q.q1A = ex2f(fmaf(eA1.x, L2E, lpiA));
        q.q1B = ex2f(fmaf(eB1.x, L2E, lpiB));
        q00[l] = pack_bf16x2(q.q0A, q.q0B);
        q10[l] = pack_bf16x2(q.q1A, q.q1B);
        stepPair(q00, q01, q10, q11, l, Ta, Tb, eA0.y, eB0.y, eA1.y, eB1.y, 0.f, 0.f, q);
        stepPair(q01, q00, q11, q10, l, Ta, Tb, eA0.z, eB0.z, eA1.z, eB1.z, 0.f, 0.f, q);
        stepPair(q00, q01, q10, q11, l, Ta, Tb, eA0.w, eB0.w, eA1.w, eB1.w, 0.f, 0.f, q);
#pragma unroll 1
        for (int g = 1; g < 4; g++)
            group4(sb0, sb1, 4 * g, l, q00, q01, q10, q11, Ta, Tb, 0.f, 0.f, q);
        // prefetch block 2 into buf 0 (block 0 fully consumed)
        stage(st[0][0], base0 + 2 * TBLK, l);
        stage(st[1][0], base1 + 2 * TBLK, l);
        commit_group();
        float S0 = warp_sum(q.q0A + q.q0B);
        float S1 = warp_sum(q.q1A + q.q1B);
        float g0 = lg2f(S0), g1 = lg2f(S1);
        c0 += g0; c1 += g1; gp0 = -g0; gp1 = -g1;
    }

#pragma unroll 1
    for (int blk = 1; blk < NBLK; blk++) {
        if (blk == NBLK - 1) wait_group<0>(); else wait_group<1>();
        __syncwarp();
        const float* sb0 = st[0][blk & 1];
        const float* sb1 = st[1][blk & 1];
#pragma unroll 1
        for (int g = 0; g < 4; g++)
            group4(sb0, sb1, 4 * g, l, q00, q01, q10, q11, Ta, Tb,
                   g == 0 ? gp0 : 0.f, g == 0 ? gp1 : 0.f, q);
        if (blk < NBLK - 2) {
            stage(st[0][blk & 1], base0 + (size_t)(blk + 2) * TBLK, l);
            stage(st[1][blk & 1], base1 + (size_t)(blk + 2) * TBLK, l);
            commit_group();
        }
        if (blk < NBLK - 1) {
            float S0 = warp_sum(q.q0A + q.q0B);
            float S1 = warp_sum(q.q1A + q.q1B);
            float g0 = lg2f(S0), g1 = lg2f(S1);
            c0 += g0; c1 += g1; gp0 = -g0; gp1 = -g1;
        } else {
            gp0 = 0.f; gp1 = 0.f;
        }
    }

    float S0 = warp_sum(q.q0A + q.q0B);
    float S1 = warp_sum(q.q1A + q.q1B);
    if (l == 0) {
        gPart[2 * blockIdx.x]     = LN2 * (c0 + lg2f(S0));
        gPart[2 * blockIdx.x + 1] = LN2 * (c1 + lg2f(S1));
    }
}

// ---------------------------------------------------------------------------
// deterministic final reduction
// ---------------------------------------------------------------------------
__global__ void reduce_kernel(float* __restrict__ out) {
    __shared__ double s[256];
    int t = threadIdx.x;
    double v = 0.0;
    for (int i = t; i < Bseq; i += 256) v += (double)gPart[i];
    s[t] = v;
    __syncthreads();
    for (int o = 128; o > 0; o >>= 1) {
        if (t < o) s[t] += s[t + o];
        __syncthreads();
    }
    if (t == 0) out[0] = (float)s[0];
}

// ---------------------------------------------------------------------------
extern "C" void kernel_launch(void* const* d_in, const int* in_sizes, int n_in,
                              void* d_out, int out_size) {
    const float* lp = (const float*)d_in[0];  // log_pdf (K, N)
    const float* pi = (const float*)d_in[1];  // pi (K,)
    const float* T  = (const float*)d_in[2];  // T (K, K)
    (void)in_sizes; (void)n_in; (void)out_size;

    prep_kernel<<<1, 1024>>>(pi, T);
    fwd_kernel<<<Bseq / 2, 32>>>(lp);
    reduce_kernel<<<1, 256>>>((float*)d_out);
}

// round 6
// speedup vs baseline: 1.0157x; 1.0157x over previous
#include <cuda_runtime.h>
#include <cstddef>

// Fixed problem shape: K=64, N=1048576, NS=1024, B=1024
constexpr int   Kdim   = 64;
constexpr long  Nn     = 1048576;
constexpr int   NSs    = 1024;
constexpr int   Bseq   = 1024;
constexpr int   TBLK   = 32;          // staging block (time steps)
constexpr int   STRIDE = 36;          // staged row stride (floats), 16B-aligned rows
constexpr float L2E    = 1.4426950408889634f;
constexpr float LN2    = 0.6931471805599453f;

__device__ unsigned gT2[Kdim * 32];   // gT2[k*32+j] = bf16x2(Tp[2j][k], Tp[2j+1][k])
__device__ float    gTpF[Kdim * Kdim]; // fp32 row-softmax of T (for bias kernel)
__device__ float    gLpi2[Kdim];      // log_softmax(pi) * log2(e)
__device__ float    gLs[Kdim];        // per-state log2 correction for bf16(T) bias
__device__ float    gPart[Bseq];

// ---------------------------------------------------------------------------
// helpers
// ---------------------------------------------------------------------------
__device__ __forceinline__ float ex2f(float x) {
    float r; asm("ex2.approx.ftz.f32 %0, %1;" : "=f"(r) : "f"(x)); return r;
}
__device__ __forceinline__ float lg2f(float x) {
    float r; asm("lg2.approx.ftz.f32 %0, %1;" : "=f"(r) : "f"(x)); return r;
}
__device__ __forceinline__ float warp_sum(float v) {
#pragma unroll
    for (int o = 16; o > 0; o >>= 1) v += __shfl_xor_sync(0xffffffffu, v, o);
    return v;
}
__device__ __forceinline__ void hfma2(unsigned& acc, unsigned a, unsigned b) {
    asm("fma.rn.bf16x2 %0, %1, %2, %0;" : "+r"(acc) : "r"(a), "r"(b));
}
__device__ __forceinline__ unsigned hadd2(unsigned a, unsigned b) {
    unsigned r; asm("add.rn.bf16x2 %0, %1, %2;" : "=r"(r) : "r"(a), "r"(b)); return r;
}
__device__ __forceinline__ float blo(unsigned u) { return __uint_as_float(u << 16); }
__device__ __forceinline__ float bhi(unsigned u) { return __uint_as_float(u & 0xffff0000u); }
__device__ __forceinline__ unsigned pack_bf16x2(float lo, float hi) {
    unsigned r; asm("cvt.rn.bf16x2.f32 %0, %1, %2;" : "=r"(r) : "f"(hi), "f"(lo)); return r;
}
__device__ __forceinline__ float bf16r(float x) { return blo(pack_bf16x2(x, 0.f)); }
__device__ __forceinline__ void cpasync16(void* dst, const void* src) {
    unsigned d = (unsigned)__cvta_generic_to_shared(dst);
    asm volatile("cp.async.ca.shared.global [%0], [%1], 16;" :: "r"(d), "l"(src));
}
template <int N> __device__ __forceinline__ void wait_group() {
    asm volatile("cp.async.wait_group %0;" :: "n"(N));
}
__device__ __forceinline__ void commit_group() {
    asm volatile("cp.async.commit_group;");
}

// stage one 32-step emission block (64 rows x 32 floats) + commit
__device__ __forceinline__ void issue_stage(float* sbuf, const float* gbase, int l) {
#pragma unroll
    for (int i = 0; i < 16; i++) {
        int m   = (i << 5) + l;
        int row = m >> 3;
        int c4  = (m & 7) << 2;
        cpasync16(sbuf + row * STRIDE + c4, gbase + (size_t)row * Nn + c4);
    }
    commit_group();
}

// ---------------------------------------------------------------------------
// prep: softmax rows of T -> fp32 copy + bf16x2 pack; log_softmax(pi)
// ---------------------------------------------------------------------------
__global__ void __launch_bounds__(1024) prep_kernel(const float* __restrict__ pi,
                                                    const float* __restrict__ T) {
    __shared__ float sTp[Kdim * Kdim];
    int tid = threadIdx.x, w = tid >> 5, l = tid & 31;
#pragma unroll
    for (int r = w; r < Kdim; r += 32) {
        float a = T[r * Kdim + l], c = T[r * Kdim + l + 32];
        float m = fmaxf(a, c);
#pragma unroll
        for (int o = 16; o > 0; o >>= 1) m = fmaxf(m, __shfl_xor_sync(0xffffffffu, m, o));
        float ea = expf(a - m), ec = expf(c - m);
        float s = warp_sum(ea + ec);
        float inv = 1.0f / s;
        sTp[r * Kdim + l]      = ea * inv;
        sTp[r * Kdim + l + 32] = ec * inv;
    }
    __syncthreads();
    for (int idx = tid; idx < Kdim * Kdim; idx += 1024) gTpF[idx] = sTp[idx];
    for (int idx = tid; idx < Kdim * 32; idx += 1024) {
        int k = idx >> 5, j = idx & 31;
        gT2[idx] = pack_bf16x2(sTp[(2 * j) * Kdim + k], sTp[(2 * j + 1) * Kdim + k]);
    }
    if (w == 0) {  // log_softmax(pi)
        float pa = pi[l], pb = pi[l + 32];
        float m2 = fmaxf(pa, pb);
#pragma unroll
        for (int o = 16; o > 0; o >>= 1) m2 = fmaxf(m2, __shfl_xor_sync(0xffffffffu, m2, o));
        float sp = warp_sum(expf(pa - m2) + expf(pb - m2));
        float ls = logf(sp);
        gLpi2[l]      = (pa - m2 - ls) * L2E;
        gLpi2[l + 32] = (pb - m2 - ls) * L2E;
    }
}

// ---------------------------------------------------------------------------
// bias kernel (single warp, register-unconstrained):
// stationary distribution of Tp + per-column log2 correction for bf16(T) bias
// ---------------------------------------------------------------------------
__global__ void bias_kernel() {
    int l = threadIdx.x;
    float wA = 1.0f / 64.0f, wB = 1.0f / 64.0f;
    for (int it = 0; it < 24; it++) {
        float nA = 0.f, nB = 0.f;
#pragma unroll
        for (int j = 0; j < 32; j++) {
            float wj0 = __shfl_sync(0xffffffffu, wA, j);
            float wj1 = __shfl_sync(0xffffffffu, wB, j);
            nA = fmaf(wj0, gTpF[(2 * j) * Kdim + 2 * l],     nA);
            nA = fmaf(wj1, gTpF[(2 * j + 1) * Kdim + 2 * l], nA);
            nB = fmaf(wj0, gTpF[(2 * j) * Kdim + 2 * l + 1],     nB);
            nB = fmaf(wj1, gTpF[(2 * j + 1) * Kdim + 2 * l + 1], nB);
        }
        float S = warp_sum(nA + nB);
        wA = nA / S; wB = nB / S;
    }
    float nA = 0.f, nB = 0.f, dA = 0.f, dB = 0.f;
#pragma unroll
    for (int j = 0; j < 32; j++) {
        float wj0 = __shfl_sync(0xffffffffu, wA, j);
        float wj1 = __shfl_sync(0xffffffffu, wB, j);
        float t00 = gTpF[(2 * j) * Kdim + 2 * l];
        float t10 = gTpF[(2 * j + 1) * Kdim + 2 * l];
        float t01 = gTpF[(2 * j) * Kdim + 2 * l + 1];
        float t11 = gTpF[(2 * j + 1) * Kdim + 2 * l + 1];
        nA += wj0 * t00 + wj1 * t10;
        nB += wj0 * t01 + wj1 * t11;
        dA += wj0 * bf16r(t00) + wj1 * bf16r(t10);
        dB += wj0 * bf16r(t01) + wj1 * bf16r(t11);
    }
    gLs[2 * l]     = log2f(nA / dA);
    gLs[2 * l + 1] = log2f(nB / dB);
}

// ---------------------------------------------------------------------------
// one forward step: q broadcast via shfl (no smem, no barrier)
// lane l owns states (2l, 2l+1); qp = bf16x2(q_{2l}, q_{2l+1})
// ---------------------------------------------------------------------------
__device__ __forceinline__ void stepS(unsigned& qp,
                                      const unsigned* __restrict__ Ta,
                                      const unsigned* __restrict__ Tb,
                                      float fA, float fB,
                                      float& qA, float& qB) {
    unsigned A0 = 0, A1 = 0, A2 = 0, A3 = 0;
    unsigned B0 = 0, B1 = 0, B2 = 0, B3 = 0;
#pragma unroll
    for (int j = 0; j < 32; j += 4) {
        unsigned w0 = __shfl_sync(0xffffffffu, qp, j);
        unsigned w1 = __shfl_sync(0xffffffffu, qp, j + 1);
        unsigned w2 = __shfl_sync(0xffffffffu, qp, j + 2);
        unsigned w3 = __shfl_sync(0xffffffffu, qp, j + 3);
        hfma2(A0, w0, Ta[j]);     hfma2(B0, w0, Tb[j]);
        hfma2(A1, w1, Ta[j + 1]); hfma2(B1, w1, Tb[j + 1]);
        hfma2(A2, w2, Ta[j + 2]); hfma2(B2, w2, Tb[j + 2]);
        hfma2(A3, w3, Ta[j + 3]); hfma2(B3, w3, Tb[j + 3]);
    }
    unsigned a = hadd2(hadd2(A0, A1), hadd2(A2, A3));
    unsigned b = hadd2(hadd2(B0, B1), hadd2(B2, B3));
    qA = fA * (blo(a) + bhi(a));
    qB = fB * (blo(b) + bhi(b));
    qp = pack_bf16x2(qA, qB);
}

// ---------------------------------------------------------------------------
// forward scan: one single-warp CTA per sequence (1024 CTAs)
// ---------------------------------------------------------------------------
__global__ void __launch_bounds__(32) fwd_kernel(const float* __restrict__ lp) {
    __shared__ float st[2][Kdim * STRIDE];   // 18432 B
    const int l = threadIdx.x;
    const float* base = lp + (size_t)blockIdx.x * NSs;

    issue_stage(st[0], base, l);
    issue_stage(st[1], base + TBLK, l);

    unsigned Ta[32], Tb[32];
    {
        const uint4* pa = (const uint4*)(gT2 + (2 * l) * 32);
        const uint4* pb = (const uint4*)(gT2 + (2 * l + 1) * 32);
#pragma unroll
        for (int i = 0; i < 8; i++) { ((uint4*)Ta)[i] = pa[i]; ((uint4*)Tb)[i] = pb[i]; }
    }
    const float lpiA = gLpi2[2 * l], lpiB = gLpi2[2 * l + 1];
    const float lsA  = gLs[2 * l],   lsB  = gLs[2 * l + 1];

    wait_group<1>();
    __syncwarp();

    // t = 0..3
    float4 e4A = *(const float4*)(st[0] + (2 * l) * STRIDE);
    float4 e4B = *(const float4*)(st[0] + (2 * l + 1) * STRIDE);
    float qA = ex2f(fmaf(e4A.x, L2E, lpiA));
    float qB = ex2f(fmaf(e4B.x, L2E, lpiB));
    unsigned qp = pack_bf16x2(qA, qB);
    {
        float fA1 = ex2f(fmaf(e4A.y, L2E, lsA)), fB1 = ex2f(fmaf(e4B.y, L2E, lsB));
        float fA2 = ex2f(fmaf(e4A.z, L2E, lsA)), fB2 = ex2f(fmaf(e4B.z, L2E, lsB));
        float fA3 = ex2f(fmaf(e4A.w, L2E, lsA)), fB3 = ex2f(fmaf(e4B.w, L2E, lsB));
        stepS(qp, Ta, Tb, fA1, fB1, qA, qB);
        stepS(qp, Ta, Tb, fA2, fB2, qA, qB);
        stepS(qp, Ta, Tb, fA3, fB3, qA, qB);
    }

    double cacc = 0.0;
    float  gp   = 0.0f;

#pragma unroll 1
    for (int t0 = 4; t0 < NSs; t0 += 4) {
        if ((t0 & (TBLK - 1)) == 0) {
            wait_group<0>();
            __syncwarp();
            int k = t0 >> 5;                     // current block index
            if (t0 + TBLK < NSs)
                issue_stage(st[(k + 1) & 1], base + t0 + TBLK, l);
        }
        const float* sb = st[(t0 >> 5) & 1];
        const int tt = t0 & (TBLK - 1);
        float4 eA = *(const float4*)(sb + (2 * l) * STRIDE + tt);
        float4 eB = *(const float4*)(sb + (2 * l + 1) * STRIDE + tt);

        // off-chain f-factor precompute (bias correction + pending renorm)
        float aA = lsA + gp, aB = lsB + gp;
        float fA0 = ex2f(fmaf(eA.x, L2E, aA)),  fB0 = ex2f(fmaf(eB.x, L2E, aB));
        float fA1 = ex2f(fmaf(eA.y, L2E, lsA)), fB1 = ex2f(fmaf(eB.y, L2E, lsB));
        float fA2 = ex2f(fmaf(eA.z, L2E, lsA)), fB2 = ex2f(fmaf(eB.z, L2E, lsB));
        float fA3 = ex2f(fmaf(eA.w, L2E, lsA)), fB3 = ex2f(fmaf(eB.w, L2E, lsB));
        gp = 0.0f;

        stepS(qp, Ta, Tb, fA0, fB0, qA, qB);
        stepS(qp, Ta, Tb, fA1, fB1, qA, qB);
        stepS(qp, Ta, Tb, fA2, fB2, qA, qB);
        stepS(qp, Ta, Tb, fA3, fB3, qA, qB);

        if (((t0 + 4) & 15) == 0 && (t0 + 4) < NSs) {   // renorm every 16 steps
            float S = warp_sum(qA + qB);
            float g = lg2f(S);
            cacc += (double)g;
            gp = -g;
        }
    }

    float S = warp_sum(qA + qB);
    if (l == 0) gPart[blockIdx.x] = LN2 * (float)(cacc + (double)lg2f(S));
}

// ---------------------------------------------------------------------------
// deterministic final reduction
// ---------------------------------------------------------------------------
__global__ void reduce_kernel(float* __restrict__ out) {
    __shared__ double s[256];
    int t = threadIdx.x;
    double v = 0.0;
    for (int i = t; i < Bseq; i += 256) v += (double)gPart[i];
    s[t] = v;
    __syncthreads();
    for (int o = 128; o > 0; o >>= 1) {
        if (t < o) s[t] += s[t + o];
        __syncthreads();
    }
    if (t == 0) out[0] = (float)s[0];
}

// ---------------------------------------------------------------------------
extern "C" void kernel_launch(void* const* d_in, const int* in_sizes, int n_in,
                              void* d_out, int out_size) {
    const float* lp = (const float*)d_in[0];  // log_pdf (K, N)
    const float* pi = (const float*)d_in[1];  // pi (K,)
    const float* T  = (const float*)d_in[2];  // T (K, K)
    (void)in_sizes; (void)n_in; (void)out_size;

    prep_kernel<<<1, 1024>>>(pi, T);
    bias_kernel<<<1, 32>>>();
    fwd_kernel<<<Bseq, 32>>>(lp);
    reduce_kernel<<<1, 256>>>((float*)d_out);
}